// round 1
// baseline (speedup 1.0000x reference)
#include <cuda_runtime.h>
#include <cuda_bf16.h>

// Problem constants
#define B_   16
#define N_   2048
#define F_   64
#define HD_  256
#define K_   128
#define G_   18
#define FUSE_ 274

// Scratch (allocation-free rule: __device__ globals)
__device__ float g_buf1[B_ * N_ * HD_];   // 32 MB
__device__ float g_buf2[B_ * N_ * HD_];   // 32 MB
__device__ float g_partial[B_ * 16 * HD_];

// ---------------------------------------------------------------------------
// Generic batched SGEMM: C[b] = A[b] @ Bm[b]
// BM=128, BN=64, BK=32, 256 threads, 8x4 per-thread microtile.
// A row-major (M x Kd), Bm row-major (Kd x Ncols), C row-major (M x Ncols).
// Requires M%128==0, Ncols%64==0, Kd%32==0 (all hold here).
// ---------------------------------------------------------------------------
#define BM 128
#define BN 64
#define BK 32
#define TM 8
#define TN 4

__global__ __launch_bounds__(256, 3)
void sgemm_kernel(const float* __restrict__ A, const float* __restrict__ Bm,
                  float* __restrict__ C, int M, int Kd, int Ncols,
                  long long sA, long long sB, long long sC) {
    const long long bz = blockIdx.z;
    A  += bz * sA;
    Bm += bz * sB;
    C  += bz * sC;

    const int bm = blockIdx.y * BM;
    const int bn = blockIdx.x * BN;

    __shared__ float As[BK][BM + 4];   // transposed A tile, +4 pad (vector-load aligned)
    __shared__ float Bs[BK][BN];

    const int tid = threadIdx.x;
    const int tx = tid & 15;   // n direction (16 * TN = 64)
    const int ty = tid >> 4;   // m direction (16 * TM = 128)

    float acc[TM][TN];
#pragma unroll
    for (int i = 0; i < TM; i++)
#pragma unroll
        for (int j = 0; j < TN; j++) acc[i][j] = 0.f;

    for (int k0 = 0; k0 < Kd; k0 += BK) {
        // Load A tile (128 rows x 32 cols) as float4, store transposed.
#pragma unroll
        for (int i = 0; i < 4; i++) {
            int idx = tid + i * 256;          // 0..1023
            int r   = idx >> 3;               // row in tile (0..127)
            int c4  = idx & 7;                // float4 col (0..7)
            float4 v = *reinterpret_cast<const float4*>(
                &A[(long long)(bm + r) * Kd + k0 + c4 * 4]);
            As[c4 * 4 + 0][r] = v.x;
            As[c4 * 4 + 1][r] = v.y;
            As[c4 * 4 + 2][r] = v.z;
            As[c4 * 4 + 3][r] = v.w;
        }
        // Load B tile (32 rows x 64 cols) as float4.
#pragma unroll
        for (int i = 0; i < 2; i++) {
            int idx = tid + i * 256;          // 0..511
            int r   = idx >> 4;               // k row (0..31)
            int c4  = idx & 15;               // float4 col (0..15)
            float4 v = *reinterpret_cast<const float4*>(
                &Bm[(long long)(k0 + r) * Ncols + bn + c4 * 4]);
            *reinterpret_cast<float4*>(&Bs[r][c4 * 4]) = v;
        }
        __syncthreads();

#pragma unroll
        for (int k = 0; k < BK; k++) {
            float a[TM], b[TN];
#pragma unroll
            for (int i = 0; i < TM; i++) a[i] = As[k][ty * TM + i];
#pragma unroll
            for (int j = 0; j < TN; j++) b[j] = Bs[k][tx * TN + j];
#pragma unroll
            for (int i = 0; i < TM; i++)
#pragma unroll
                for (int j = 0; j < TN; j++) acc[i][j] += a[i] * b[j];
        }
        __syncthreads();
    }

#pragma unroll
    for (int i = 0; i < TM; i++) {
        long long r = bm + ty * TM + i;
        float4 v = make_float4(acc[i][0], acc[i][1], acc[i][2], acc[i][3]);
        *reinterpret_cast<float4*>(&C[r * Ncols + bn + tx * TN]) = v;
    }
}

// ---------------------------------------------------------------------------
// bias + LayerNorm(256) + ReLU, one block (256 threads) per row
// ---------------------------------------------------------------------------
__global__ __launch_bounds__(256)
void bias_ln_relu_kernel(const float* __restrict__ Z, const float* __restrict__ bias,
                         const float* __restrict__ gamma, const float* __restrict__ beta,
                         float* __restrict__ out) {
    const long long row = blockIdx.x;
    const int f = threadIdx.x;
    float x = Z[row * HD_ + f] + bias[f];

    float s = x, s2 = x * x;
#pragma unroll
    for (int o = 16; o; o >>= 1) {
        s  += __shfl_xor_sync(0xFFFFFFFFu, s, o);
        s2 += __shfl_xor_sync(0xFFFFFFFFu, s2, o);
    }
    __shared__ float ws[8], ws2[8];
    int w = f >> 5, l = f & 31;
    if (l == 0) { ws[w] = s; ws2[w] = s2; }
    __syncthreads();
    if (w == 0) {
        float a  = (l < 8) ? ws[l]  : 0.f;
        float a2 = (l < 8) ? ws2[l] : 0.f;
#pragma unroll
        for (int o = 4; o; o >>= 1) {
            a  += __shfl_xor_sync(0xFFFFFFFFu, a, o);
            a2 += __shfl_xor_sync(0xFFFFFFFFu, a2, o);
        }
        if (l == 0) { ws[0] = a; ws2[0] = a2; }
    }
    __syncthreads();
    const float inv = 1.f / (float)HD_;
    float mu  = ws[0] * inv;
    float var = ws2[0] * inv - mu * mu;
    float y = (x - mu) * rsqrtf(var + 1e-5f) * gamma[f] + beta[f];
    out[row * HD_ + f] = fmaxf(y, 0.f);
}

// ---------------------------------------------------------------------------
// Partial column sums for mean readout: grid (B, 16 chunks of 128 rows)
// ---------------------------------------------------------------------------
__global__ __launch_bounds__(256)
void col_partial_kernel(const float* __restrict__ H, float* __restrict__ part) {
    int b = blockIdx.x, chunk = blockIdx.y, f = threadIdx.x;
    const float* p = H + ((long long)b * N_ + (long long)chunk * 128) * HD_ + f;
    float s = 0.f;
#pragma unroll 8
    for (int n = 0; n < 128; n++) s += p[(long long)n * HD_];
    part[(b * 16 + chunk) * HD_ + f] = s;
}

// ---------------------------------------------------------------------------
// Head: reduce partials -> mean, concat global_vec, two small linear heads.
// Output layout: out[0..15] = pred_y_reg, out[16 + b*128 + k] = pred_arr_reg.
// ---------------------------------------------------------------------------
__global__ __launch_bounds__(256)
void head_kernel(const float* __restrict__ part, const float* __restrict__ gvec,
                 const float* __restrict__ Ws, const float* __restrict__ bs,
                 const float* __restrict__ Wa, const float* __restrict__ ba,
                 float* __restrict__ out) {
    int b = blockIdx.x, t = threadIdx.x;
    __shared__ float fused[FUSE_];
    float s = 0.f;
#pragma unroll
    for (int c = 0; c < 16; c++) s += part[(b * 16 + c) * HD_ + t];
    fused[t] = s * (1.f / (float)N_);
    if (t < G_) fused[HD_ + t] = gvec[b * G_ + t];
    __syncthreads();

    if (t < K_) {
        float acc = ba[t];
#pragma unroll 4
        for (int i = 0; i < FUSE_; i++) acc += fused[i] * Wa[i * K_ + t];
        out[B_ + b * K_ + t] = acc;
    } else if (t == K_) {
        float acc = bs[0];
        for (int i = 0; i < FUSE_; i++) acc += fused[i] * Ws[i];
        out[b] = acc;
    }
}

// ---------------------------------------------------------------------------
extern "C" void kernel_launch(void* const* d_in, const int* in_sizes, int n_in,
                              void* d_out, int out_size) {
    const float* A_hat = (const float*)d_in[0];
    const float* X     = (const float*)d_in[1];
    const float* gvec  = (const float*)d_in[2];
    const float* W1    = (const float*)d_in[3];
    const float* b1    = (const float*)d_in[4];
    const float* g1    = (const float*)d_in[5];
    const float* be1   = (const float*)d_in[6];
    const float* W2    = (const float*)d_in[7];
    const float* b2    = (const float*)d_in[8];
    const float* g2    = (const float*)d_in[9];
    const float* be2   = (const float*)d_in[10];
    const float* Ws    = (const float*)d_in[11];
    const float* bs    = (const float*)d_in[12];
    const float* Wa    = (const float*)d_in[13];
    const float* ba    = (const float*)d_in[14];
    float* out = (float*)d_out;

    float *buf1, *buf2, *part;
    cudaGetSymbolAddress((void**)&buf1, g_buf1);
    cudaGetSymbolAddress((void**)&buf2, g_buf2);
    cudaGetSymbolAddress((void**)&part, g_partial);

    dim3 blk(256);

    // K1: T1 = A_hat @ X        (per batch 2048x2048 @ 2048x64) -> buf1
    sgemm_kernel<<<dim3(1, 16, 16), blk>>>(A_hat, X, buf1, N_, N_, F_,
                                           (long long)N_ * N_, (long long)N_ * F_,
                                           (long long)N_ * F_);
    // K2a: Z1 = T1 @ W1          (flattened 32768x64 @ 64x256) -> buf2
    sgemm_kernel<<<dim3(4, 256, 1), blk>>>(buf1, W1, buf2, B_ * N_, F_, HD_, 0, 0, 0);
    // K2b: H1 = relu(LN(Z1 + b1)) -> buf1
    bias_ln_relu_kernel<<<B_ * N_, 256>>>(buf2, b1, g1, be1, buf1);
    // K3: T2 = A_hat @ H1        (per batch 2048x2048 @ 2048x256) -> buf2
    sgemm_kernel<<<dim3(4, 16, 16), blk>>>(A_hat, buf1, buf2, N_, N_, HD_,
                                           (long long)N_ * N_, (long long)N_ * HD_,
                                           (long long)N_ * HD_);
    // K4a: Z2 = T2 @ W2          (32768x256 @ 256x256) -> buf1
    sgemm_kernel<<<dim3(4, 256, 1), blk>>>(buf2, W2, buf1, B_ * N_, HD_, HD_, 0, 0, 0);
    // K4b: H2 = relu(LN(Z2 + b2)) -> buf2
    bias_ln_relu_kernel<<<B_ * N_, 256>>>(buf1, b2, g2, be2, buf2);
    // K5: partial column sums -> part
    col_partial_kernel<<<dim3(B_, 16), 256>>>(buf2, part);
    // K6: mean + concat + heads -> out
    head_kernel<<<B_, 256>>>(part, gvec, Ws, bs, Wa, ba, out);
}

// round 3
// speedup vs baseline: 2.5203x; 2.5203x over previous
#include <cuda_runtime.h>
#include <cstdint>

// Problem constants
#define B_   16
#define N_   2048
#define F_   64
#define HD_  256
#define K_   128
#define G_   18
#define FUSE_ 274

// Scratch (allocation-free rule: __device__ globals)
__device__ float g_buf1[B_ * N_ * HD_];   // 32 MB
__device__ float g_buf2[B_ * N_ * HD_];   // 32 MB
__device__ float g_partial[B_ * 16 * HD_];

// ---------------------------------------------------------------------------
// Helpers (baseline PTX only — the harness compiles for compute_103 WITHOUT
// the 'a' feature suffix, so no tcgen05/TMEM; mma.sync + cp.async are fine)
// ---------------------------------------------------------------------------
__device__ __forceinline__ uint32_t smem_u32(const void* p) {
    uint32_t a;
    asm("{ .reg .u64 t; cvta.to.shared.u64 t, %1; cvt.u32.u64 %0, t; }"
        : "=r"(a) : "l"(p));
    return a;
}

__device__ __forceinline__ void cp16(uint32_t dst, const float* src) {
    asm volatile("cp.async.cg.shared.global [%0], [%1], 16;"
                 :: "r"(dst), "l"(src) : "memory");
}
#define CP_COMMIT() asm volatile("cp.async.commit_group;" ::: "memory")
#define CP_WAIT0()  asm volatile("cp.async.wait_group 0;" ::: "memory")

__device__ __forceinline__ uint32_t cvt_tf32(float f) {
    uint32_t u;
    asm("cvt.rna.tf32.f32 %0, %1;" : "=r"(u) : "f"(f));
    return u;
}

__device__ __forceinline__ void mma8(float* c, const uint32_t* a, const uint32_t* b) {
    asm volatile(
        "mma.sync.aligned.m16n8k8.row.col.f32.tf32.tf32.f32 "
        "{%0,%1,%2,%3}, {%4,%5,%6,%7}, {%8,%9}, {%0,%1,%2,%3};"
        : "+f"(c[0]), "+f"(c[1]), "+f"(c[2]), "+f"(c[3])
        : "r"(a[0]), "r"(a[1]), "r"(a[2]), "r"(a[3]), "r"(b[0]), "r"(b[1]));
}

// ---------------------------------------------------------------------------
// TF32 mma.sync GEMM: C[bz] = A[bz] @ Bm[bz]
// BM=128, BK=32, BN template (64/128). 256 threads = 8 warps.
// Warp grid WROWS x WCOLS; warp tile (128/WROWS) x (BN/WCOLS).
// A row-major [M x Kd], Bm row-major [Kd x Ncols], C row-major [M x Ncols].
// Double-buffered cp.async pipeline.
// ---------------------------------------------------------------------------
template <int BN, int WROWS, int WCOLS>
__global__ __launch_bounds__(256)
void tf32_mma_gemm(const float* __restrict__ A, const float* __restrict__ Bm,
                   float* __restrict__ C, int Kd, int Ncols,
                   long long sA, long long sB, long long sC) {
    constexpr int BM = 128, BK = 32;
    constexpr int WM = BM / WROWS, WN = BN / WCOLS;
    constexpr int MF = WM / 16, NF = WN / 8;
    constexpr int AP = 36;          // A smem pitch (floats): bank = (4m+k)%32
    constexpr int BP = BN + 8;      // B smem pitch: bank = (8k+n)%32
    constexpr int AS_F = BM * AP;   // 4608 floats / stage
    constexpr int BS_F = BK * BP;

    extern __shared__ float smem[];
    const uint32_t sbase = smem_u32(smem);

    const int tid  = threadIdx.x;
    const int lane = tid & 31, wid = tid >> 5;
    const int wm = (wid / WCOLS) * WM;
    const int wn = (wid % WCOLS) * WN;

    const long long bz = blockIdx.z;
    const float* Ab = A + bz * sA + (long long)blockIdx.y * BM * Kd;
    const float* Bb = Bm + bz * sB + blockIdx.x * BN;
    float*       Cb = C + bz * sC + (long long)blockIdx.y * BM * Ncols
                        + blockIdx.x * BN;

    float acc[MF][NF][4];
#pragma unroll
    for (int i = 0; i < MF; i++)
#pragma unroll
        for (int j = 0; j < NF; j++)
#pragma unroll
            for (int r = 0; r < 4; r++) acc[i][j][r] = 0.f;

    const int nch = Kd >> 5;

    auto load_stage = [&](int s, int kc) {
        const float* Ak = Ab + kc * BK;
#pragma unroll
        for (int i = 0; i < 4; i++) {
            int idx = tid + i * 256;
            int r = idx >> 3, c4 = idx & 7;
            uint32_t dst = sbase + (uint32_t)(s * AS_F + r * AP + c4 * 4) * 4u;
            cp16(dst, Ak + (long long)r * Kd + c4 * 4);
        }
        const float* Bk = Bb + (long long)(kc * BK) * Ncols;
        constexpr int BI = (BN * BK) / (4 * 256);
        constexpr int C4 = BN / 4;
#pragma unroll
        for (int i = 0; i < BI; i++) {
            int idx = tid + i * 256;
            int r = idx / C4, c4 = idx % C4;
            uint32_t dst = sbase +
                (uint32_t)(2 * AS_F + s * BS_F + r * BP + c4 * 4) * 4u;
            cp16(dst, Bk + (long long)r * Ncols + c4 * 4);
        }
    };

    auto compute_stage = [&](int s) {
        const float* As = smem + s * AS_F;
        const float* Bs = smem + 2 * AS_F + s * BS_F;
#pragma unroll
        for (int kk = 0; kk < 4; kk++) {
            const int k0 = kk * 8;
            uint32_t af[MF][4], bf[NF][2];
#pragma unroll
            for (int mf = 0; mf < MF; mf++) {
                int m = wm + mf * 16 + (lane >> 2);
                int k = k0 + (lane & 3);
                af[mf][0] = cvt_tf32(As[m * AP + k]);
                af[mf][1] = cvt_tf32(As[(m + 8) * AP + k]);
                af[mf][2] = cvt_tf32(As[m * AP + k + 4]);
                af[mf][3] = cvt_tf32(As[(m + 8) * AP + k + 4]);
            }
#pragma unroll
            for (int nf = 0; nf < NF; nf++) {
                int n = wn + nf * 8 + (lane >> 2);
                int k = k0 + (lane & 3);
                bf[nf][0] = cvt_tf32(Bs[k * BP + n]);
                bf[nf][1] = cvt_tf32(Bs[(k + 4) * BP + n]);
            }
#pragma unroll
            for (int mf = 0; mf < MF; mf++)
#pragma unroll
                for (int nf = 0; nf < NF; nf++)
                    mma8(acc[mf][nf], af[mf], bf[nf]);
        }
    };

    load_stage(0, 0);
    CP_COMMIT();
    for (int kc = 0; kc < nch; kc++) {
        CP_WAIT0();
        __syncthreads();
        if (kc + 1 < nch) { load_stage((kc + 1) & 1, kc + 1); CP_COMMIT(); }
        compute_stage(kc & 1);
    }

    // Epilogue: c0/c1 at (row, col..col+1), c2/c3 at (row+8, ...)
#pragma unroll
    for (int mf = 0; mf < MF; mf++) {
#pragma unroll
        for (int nf = 0; nf < NF; nf++) {
            int row = wm + mf * 16 + (lane >> 2);
            int col = wn + nf * 8 + (lane & 3) * 2;
            float2 v0 = make_float2(acc[mf][nf][0], acc[mf][nf][1]);
            float2 v1 = make_float2(acc[mf][nf][2], acc[mf][nf][3]);
            *reinterpret_cast<float2*>(Cb + (long long)row * Ncols + col) = v0;
            *reinterpret_cast<float2*>(Cb + (long long)(row + 8) * Ncols + col) = v1;
        }
    }
}

// ---------------------------------------------------------------------------
// bias + LayerNorm(256) + ReLU, one block (256 threads) per row
// ---------------------------------------------------------------------------
__global__ __launch_bounds__(256)
void bias_ln_relu_kernel(const float* __restrict__ Z, const float* __restrict__ bias,
                         const float* __restrict__ gamma, const float* __restrict__ beta,
                         float* __restrict__ out) {
    const long long row = blockIdx.x;
    const int f = threadIdx.x;
    float x = Z[row * HD_ + f] + bias[f];

    float s = x, s2 = x * x;
#pragma unroll
    for (int o = 16; o; o >>= 1) {
        s  += __shfl_xor_sync(0xFFFFFFFFu, s, o);
        s2 += __shfl_xor_sync(0xFFFFFFFFu, s2, o);
    }
    __shared__ float ws[8], ws2[8];
    int w = f >> 5, l = f & 31;
    if (l == 0) { ws[w] = s; ws2[w] = s2; }
    __syncthreads();
    if (w == 0) {
        float a  = (l < 8) ? ws[l]  : 0.f;
        float a2 = (l < 8) ? ws2[l] : 0.f;
#pragma unroll
        for (int o = 4; o; o >>= 1) {
            a  += __shfl_xor_sync(0xFFFFFFFFu, a, o);
            a2 += __shfl_xor_sync(0xFFFFFFFFu, a2, o);
        }
        if (l == 0) { ws[0] = a; ws2[0] = a2; }
    }
    __syncthreads();
    const float inv = 1.f / (float)HD_;
    float mu  = ws[0] * inv;
    float var = ws2[0] * inv - mu * mu;
    float y = (x - mu) * rsqrtf(var + 1e-5f) * gamma[f] + beta[f];
    out[row * HD_ + f] = fmaxf(y, 0.f);
}

// ---------------------------------------------------------------------------
// Partial column sums for mean readout: grid (B, 16 chunks of 128 rows)
// ---------------------------------------------------------------------------
__global__ __launch_bounds__(256)
void col_partial_kernel(const float* __restrict__ H, float* __restrict__ part) {
    int b = blockIdx.x, chunk = blockIdx.y, f = threadIdx.x;
    const float* p = H + ((long long)b * N_ + (long long)chunk * 128) * HD_ + f;
    float s = 0.f;
#pragma unroll 8
    for (int n = 0; n < 128; n++) s += p[(long long)n * HD_];
    part[(b * 16 + chunk) * HD_ + f] = s;
}

// ---------------------------------------------------------------------------
// Head: reduce partials -> mean, concat global_vec, two small linear heads.
// ---------------------------------------------------------------------------
__global__ __launch_bounds__(256)
void head_kernel(const float* __restrict__ part, const float* __restrict__ gvec,
                 const float* __restrict__ Ws, const float* __restrict__ bs,
                 const float* __restrict__ Wa, const float* __restrict__ ba,
                 float* __restrict__ out) {
    int b = blockIdx.x, t = threadIdx.x;
    __shared__ float fused[FUSE_];
    float s = 0.f;
#pragma unroll
    for (int c = 0; c < 16; c++) s += part[(b * 16 + c) * HD_ + t];
    fused[t] = s * (1.f / (float)N_);
    if (t < G_) fused[HD_ + t] = gvec[b * G_ + t];
    __syncthreads();

    if (t < K_) {
        float acc = ba[t];
#pragma unroll 4
        for (int i = 0; i < FUSE_; i++) acc += fused[i] * Wa[i * K_ + t];
        out[B_ + b * K_ + t] = acc;
    } else if (t == K_) {
        float acc = bs[0];
        for (int i = 0; i < FUSE_; i++) acc += fused[i] * Ws[i];
        out[b] = acc;
    }
}

// ---------------------------------------------------------------------------
extern "C" void kernel_launch(void* const* d_in, const int* in_sizes, int n_in,
                              void* d_out, int out_size) {
    const float* A_hat = (const float*)d_in[0];
    const float* X     = (const float*)d_in[1];
    const float* gvec  = (const float*)d_in[2];
    const float* W1    = (const float*)d_in[3];
    const float* b1    = (const float*)d_in[4];
    const float* g1    = (const float*)d_in[5];
    const float* be1   = (const float*)d_in[6];
    const float* W2    = (const float*)d_in[7];
    const float* b2    = (const float*)d_in[8];
    const float* g2    = (const float*)d_in[9];
    const float* be2   = (const float*)d_in[10];
    const float* Ws    = (const float*)d_in[11];
    const float* bs    = (const float*)d_in[12];
    const float* Wa    = (const float*)d_in[13];
    const float* ba    = (const float*)d_in[14];
    float* out = (float*)d_out;

    float *buf1, *buf2, *part;
    cudaGetSymbolAddress((void**)&buf1, g_buf1);
    cudaGetSymbolAddress((void**)&buf2, g_buf2);
    cudaGetSymbolAddress((void**)&part, g_partial);

    // Dynamic smem: 2 stages * (A 4608 + B BK*(BN+8)) floats
    constexpr int SMEM64  = (2 * (128 * 36) + 2 * (32 * 72))  * 4;  // 55296
    constexpr int SMEM128 = (2 * (128 * 36) + 2 * (32 * 136)) * 4;  // 71680
    cudaFuncSetAttribute((const void*)tf32_mma_gemm<64, 4, 2>,
                         cudaFuncAttributeMaxDynamicSharedMemorySize, SMEM64);
    cudaFuncSetAttribute((const void*)tf32_mma_gemm<128, 2, 4>,
                         cudaFuncAttributeMaxDynamicSharedMemorySize, SMEM128);

    // K1: T1 = A_hat @ X   (per batch 2048x2048 @ 2048x64) -> buf1
    tf32_mma_gemm<64, 4, 2><<<dim3(1, 16, 16), 256, SMEM64>>>(
        A_hat, X, buf1, N_, F_,
        (long long)N_ * N_, (long long)N_ * F_, (long long)N_ * F_);
    // K2a: Z1 = T1 @ W1    (flat 32768x64 @ 64x256) -> buf2
    tf32_mma_gemm<128, 2, 4><<<dim3(2, 256, 1), 256, SMEM128>>>(
        buf1, W1, buf2, F_, HD_, 0, 0, 0);
    // K2b: H1 = relu(LN(Z1 + b1)) -> buf1
    bias_ln_relu_kernel<<<B_ * N_, 256>>>(buf2, b1, g1, be1, buf1);
    // K3: T2 = A_hat @ H1  (per batch 2048x2048 @ 2048x256) -> buf2
    tf32_mma_gemm<128, 2, 4><<<dim3(2, 16, 16), 256, SMEM128>>>(
        A_hat, buf1, buf2, N_, HD_,
        (long long)N_ * N_, (long long)N_ * HD_, (long long)N_ * HD_);
    // K4a: Z2 = T2 @ W2    (flat 32768x256 @ 256x256) -> buf1
    tf32_mma_gemm<128, 2, 4><<<dim3(2, 256, 1), 256, SMEM128>>>(
        buf2, W2, buf1, HD_, HD_, 0, 0, 0);
    // K4b: H2 = relu(LN(Z2 + b2)) -> buf2
    bias_ln_relu_kernel<<<B_ * N_, 256>>>(buf1, b2, g2, be2, buf2);
    // K5: partial column sums -> part
    col_partial_kernel<<<dim3(B_, 16), 256>>>(buf2, part);
    // K6: mean + concat + heads -> out
    head_kernel<<<B_, 256>>>(part, gvec, Ws, bs, Wa, ba, out);
}

// round 4
// speedup vs baseline: 2.8580x; 1.1340x over previous
#include <cuda_runtime.h>
#include <cstdint>

// Problem constants
#define B_   16
#define N_   2048
#define F_   64
#define HD_  256
#define K_   128
#define G_   18
#define FUSE_ 274

// Scratch (allocation-free rule: __device__ globals)
__device__ float g_buf1[B_ * N_ * HD_];   // 32 MB
__device__ float g_buf2[B_ * N_ * HD_];   // 32 MB
__device__ float g_partial[B_ * 16 * HD_];
__device__ float g_bufX[B_ * N_ * F_];    // 8 MB, tf32-rounded X
__device__ float g_bufW1[F_ * HD_];
__device__ float g_bufW2[HD_ * HD_];

// ---------------------------------------------------------------------------
// Helpers (baseline PTX only — harness compiles for compute_103 without 'a')
// ---------------------------------------------------------------------------
__device__ __forceinline__ uint32_t smem_u32(const void* p) {
    uint32_t a;
    asm("{ .reg .u64 t; cvta.to.shared.u64 t, %1; cvt.u32.u64 %0, t; }"
        : "=r"(a) : "l"(p));
    return a;
}

__device__ __forceinline__ void cp16(uint32_t dst, const float* src) {
    asm volatile("cp.async.cg.shared.global [%0], [%1], 16;"
                 :: "r"(dst), "l"(src) : "memory");
}
#define CP_COMMIT() asm volatile("cp.async.commit_group;" ::: "memory")
#define CP_WAIT(n)  asm volatile("cp.async.wait_group %0;" :: "n"(n) : "memory")

__device__ __forceinline__ float rna_tf32(float f) {
    uint32_t u;
    asm("cvt.rna.tf32.f32 %0, %1;" : "=r"(u) : "f"(f));
    return __uint_as_float(u);
}

__device__ __forceinline__ void mma8(float* c, const uint32_t* a, const uint32_t* b) {
    asm volatile(
        "mma.sync.aligned.m16n8k8.row.col.f32.tf32.tf32.f32 "
        "{%0,%1,%2,%3}, {%4,%5,%6,%7}, {%8,%9}, {%0,%1,%2,%3};"
        : "+f"(c[0]), "+f"(c[1]), "+f"(c[2]), "+f"(c[3])
        : "r"(a[0]), "r"(a[1]), "r"(a[2]), "r"(a[3]), "r"(b[0]), "r"(b[1]));
}

// ---------------------------------------------------------------------------
// Elementwise tf32 round (rna) into scratch, float4-vectorized
// ---------------------------------------------------------------------------
__global__ __launch_bounds__(256)
void round_tf32_kernel(const float* __restrict__ in, float* __restrict__ out, int n4) {
    int i = blockIdx.x * blockDim.x + threadIdx.x;
    if (i < n4) {
        float4 v = reinterpret_cast<const float4*>(in)[i];
        v.x = rna_tf32(v.x); v.y = rna_tf32(v.y);
        v.z = rna_tf32(v.z); v.w = rna_tf32(v.w);
        reinterpret_cast<float4*>(out)[i] = v;
    }
}

// ---------------------------------------------------------------------------
// TF32 mma.sync GEMM: C[bz] = A[bz] @ Bm[bz]
// BM=128, BK=32, BN template. 256 threads = 8 warps. 3-stage cp.async pipe.
// NO cvt in the hot loop: operands are consumed as raw bits (A truncated,
// B pre-rounded); optional rna rounding of C on store (RC).
// ---------------------------------------------------------------------------
template <int BN, int WROWS, int WCOLS, bool RC>
__global__ __launch_bounds__(256)
void tf32_mma_gemm(const float* __restrict__ A, const float* __restrict__ Bm,
                   float* __restrict__ C, int Kd, int Ncols,
                   long long sA, long long sB, long long sC) {
    constexpr int BM = 128, BK = 32, S = 3;
    constexpr int WM = BM / WROWS, WN = BN / WCOLS;
    constexpr int MF = WM / 16, NF = WN / 8;
    constexpr int AP = 36;          // A smem pitch: bank = (4m+k)%32, conflict-free
    constexpr int BP = BN + 8;      // B smem pitch: bank = (8k+n)%32, conflict-free
    constexpr int AS_F = BM * AP;
    constexpr int BS_F = BK * BP;
    constexpr int ST_F = AS_F + BS_F;

    extern __shared__ float smem[];
    const uint32_t sbase = smem_u32(smem);

    const int tid  = threadIdx.x;
    const int lane = tid & 31, wid = tid >> 5;
    const int wm = (wid / WCOLS) * WM;
    const int wn = (wid % WCOLS) * WN;

    const long long bz = blockIdx.z;
    const float* Ab = A + bz * sA + (long long)blockIdx.y * BM * Kd;
    const float* Bb = Bm + bz * sB + blockIdx.x * BN;
    float*       Cb = C + bz * sC + (long long)blockIdx.y * BM * Ncols
                        + blockIdx.x * BN;

    float acc[MF][NF][4];
#pragma unroll
    for (int i = 0; i < MF; i++)
#pragma unroll
        for (int j = 0; j < NF; j++)
#pragma unroll
            for (int r = 0; r < 4; r++) acc[i][j][r] = 0.f;

    const int nch = Kd >> 5;

    auto load_stage = [&](int s, int kc) {
        const float* Ak = Ab + kc * BK;
#pragma unroll
        for (int i = 0; i < 4; i++) {
            int idx = tid + i * 256;
            int r = idx >> 3, c4 = idx & 7;
            uint32_t dst = sbase + (uint32_t)(s * ST_F + r * AP + c4 * 4) * 4u;
            cp16(dst, Ak + (long long)r * Kd + c4 * 4);
        }
        const float* Bk = Bb + (long long)(kc * BK) * Ncols;
        constexpr int BI = (BN * BK) / (4 * 256);
        constexpr int C4 = BN / 4;
#pragma unroll
        for (int i = 0; i < BI; i++) {
            int idx = tid + i * 256;
            int r = idx / C4, c4 = idx % C4;
            uint32_t dst = sbase +
                (uint32_t)(s * ST_F + AS_F + r * BP + c4 * 4) * 4u;
            cp16(dst, Bk + (long long)r * Ncols + c4 * 4);
        }
    };

    auto compute_stage = [&](int s) {
        const uint32_t* As = reinterpret_cast<const uint32_t*>(smem + s * ST_F);
        const uint32_t* Bs = reinterpret_cast<const uint32_t*>(smem + s * ST_F + AS_F);
#pragma unroll
        for (int kk = 0; kk < 4; kk++) {
            const int k0 = kk * 8;
            uint32_t af[MF][4], bf[NF][2];
#pragma unroll
            for (int mf = 0; mf < MF; mf++) {
                int m = wm + mf * 16 + (lane >> 2);
                int k = k0 + (lane & 3);
                af[mf][0] = As[m * AP + k];
                af[mf][1] = As[(m + 8) * AP + k];
                af[mf][2] = As[m * AP + k + 4];
                af[mf][3] = As[(m + 8) * AP + k + 4];
            }
#pragma unroll
            for (int nf = 0; nf < NF; nf++) {
                int n = wn + nf * 8 + (lane >> 2);
                int k = k0 + (lane & 3);
                bf[nf][0] = Bs[k * BP + n];
                bf[nf][1] = Bs[(k + 4) * BP + n];
            }
#pragma unroll
            for (int mf = 0; mf < MF; mf++)
#pragma unroll
                for (int nf = 0; nf < NF; nf++)
                    mma8(acc[mf][nf], af[mf], bf[nf]);
        }
    };

    // Prologue: commit S-1 groups (empty groups keep the wait count uniform)
#pragma unroll
    for (int s = 0; s < S - 1; s++) {
        if (s < nch) load_stage(s, s);
        CP_COMMIT();
    }
    for (int kc = 0; kc < nch; kc++) {
        CP_WAIT(S - 2);
        __syncthreads();
        if (kc + S - 1 < nch) load_stage((kc + S - 1) % S, kc + S - 1);
        CP_COMMIT();
        compute_stage(kc % S);
        __syncthreads();
    }

    // Epilogue
#pragma unroll
    for (int mf = 0; mf < MF; mf++) {
#pragma unroll
        for (int nf = 0; nf < NF; nf++) {
            int row = wm + mf * 16 + (lane >> 2);
            int col = wn + nf * 8 + (lane & 3) * 2;
            float c0 = acc[mf][nf][0], c1 = acc[mf][nf][1];
            float c2 = acc[mf][nf][2], c3 = acc[mf][nf][3];
            if (RC) {
                c0 = rna_tf32(c0); c1 = rna_tf32(c1);
                c2 = rna_tf32(c2); c3 = rna_tf32(c3);
            }
            *reinterpret_cast<float2*>(Cb + (long long)row * Ncols + col) =
                make_float2(c0, c1);
            *reinterpret_cast<float2*>(Cb + (long long)(row + 8) * Ncols + col) =
                make_float2(c2, c3);
        }
    }
}

// ---------------------------------------------------------------------------
// bias + LayerNorm(256) + ReLU, one block (256 threads) per row.
// R: round output to tf32 (rna) when it feeds a GEMM B operand.
// ---------------------------------------------------------------------------
template <bool R>
__global__ __launch_bounds__(256)
void bias_ln_relu_kernel(const float* __restrict__ Z, const float* __restrict__ bias,
                         const float* __restrict__ gamma, const float* __restrict__ beta,
                         float* __restrict__ out) {
    const long long row = blockIdx.x;
    const int f = threadIdx.x;
    float x = Z[row * HD_ + f] + bias[f];

    float s = x, s2 = x * x;
#pragma unroll
    for (int o = 16; o; o >>= 1) {
        s  += __shfl_xor_sync(0xFFFFFFFFu, s, o);
        s2 += __shfl_xor_sync(0xFFFFFFFFu, s2, o);
    }
    __shared__ float ws[8], ws2[8];
    int w = f >> 5, l = f & 31;
    if (l == 0) { ws[w] = s; ws2[w] = s2; }
    __syncthreads();
    if (w == 0) {
        float a  = (l < 8) ? ws[l]  : 0.f;
        float a2 = (l < 8) ? ws2[l] : 0.f;
#pragma unroll
        for (int o = 4; o; o >>= 1) {
            a  += __shfl_xor_sync(0xFFFFFFFFu, a, o);
            a2 += __shfl_xor_sync(0xFFFFFFFFu, a2, o);
        }
        if (l == 0) { ws[0] = a; ws2[0] = a2; }
    }
    __syncthreads();
    const float inv = 1.f / (float)HD_;
    float mu  = ws[0] * inv;
    float var = ws2[0] * inv - mu * mu;
    float y = (x - mu) * rsqrtf(var + 1e-5f) * gamma[f] + beta[f];
    y = fmaxf(y, 0.f);
    if (R) y = rna_tf32(y);
    out[row * HD_ + f] = y;
}

// ---------------------------------------------------------------------------
// Partial column sums for mean readout: grid (B, 16 chunks of 128 rows)
// ---------------------------------------------------------------------------
__global__ __launch_bounds__(256)
void col_partial_kernel(const float* __restrict__ H, float* __restrict__ part) {
    int b = blockIdx.x, chunk = blockIdx.y, f = threadIdx.x;
    const float* p = H + ((long long)b * N_ + (long long)chunk * 128) * HD_ + f;
    float s = 0.f;
#pragma unroll 8
    for (int n = 0; n < 128; n++) s += p[(long long)n * HD_];
    part[(b * 16 + chunk) * HD_ + f] = s;
}

// ---------------------------------------------------------------------------
// Head: reduce partials -> mean, concat global_vec, two small linear heads.
// ---------------------------------------------------------------------------
__global__ __launch_bounds__(256)
void head_kernel(const float* __restrict__ part, const float* __restrict__ gvec,
                 const float* __restrict__ Ws, const float* __restrict__ bs,
                 const float* __restrict__ Wa, const float* __restrict__ ba,
                 float* __restrict__ out) {
    int b = blockIdx.x, t = threadIdx.x;
    __shared__ float fused[FUSE_];
    float s = 0.f;
#pragma unroll
    for (int c = 0; c < 16; c++) s += part[(b * 16 + c) * HD_ + t];
    fused[t] = s * (1.f / (float)N_);
    if (t < G_) fused[HD_ + t] = gvec[b * G_ + t];
    __syncthreads();

    if (t < K_) {
        float acc = ba[t];
#pragma unroll 4
        for (int i = 0; i < FUSE_; i++) acc += fused[i] * Wa[i * K_ + t];
        out[B_ + b * K_ + t] = acc;
    } else if (t == K_) {
        float acc = bs[0];
        for (int i = 0; i < FUSE_; i++) acc += fused[i] * Ws[i];
        out[b] = acc;
    }
}

// ---------------------------------------------------------------------------
extern "C" void kernel_launch(void* const* d_in, const int* in_sizes, int n_in,
                              void* d_out, int out_size) {
    const float* A_hat = (const float*)d_in[0];
    const float* X     = (const float*)d_in[1];
    const float* gvec  = (const float*)d_in[2];
    const float* W1    = (const float*)d_in[3];
    const float* b1    = (const float*)d_in[4];
    const float* g1    = (const float*)d_in[5];
    const float* be1   = (const float*)d_in[6];
    const float* W2    = (const float*)d_in[7];
    const float* b2    = (const float*)d_in[8];
    const float* g2    = (const float*)d_in[9];
    const float* be2   = (const float*)d_in[10];
    const float* Ws    = (const float*)d_in[11];
    const float* bs    = (const float*)d_in[12];
    const float* Wa    = (const float*)d_in[13];
    const float* ba    = (const float*)d_in[14];
    float* out = (float*)d_out;

    float *buf1, *buf2, *part, *bX, *bW1, *bW2;
    cudaGetSymbolAddress((void**)&buf1, g_buf1);
    cudaGetSymbolAddress((void**)&buf2, g_buf2);
    cudaGetSymbolAddress((void**)&part, g_partial);
    cudaGetSymbolAddress((void**)&bX,  g_bufX);
    cudaGetSymbolAddress((void**)&bW1, g_bufW1);
    cudaGetSymbolAddress((void**)&bW2, g_bufW2);

    // Dynamic smem: 3 stages * (A 128*36 + B 32*(BN+8)) floats
    constexpr int SMEM64  = 3 * (128 * 36 + 32 * 72)  * 4;  //  82944
    constexpr int SMEM128 = 3 * (128 * 36 + 32 * 136) * 4;  // 107520
    cudaFuncSetAttribute((const void*)tf32_mma_gemm<64, 4, 2, true>,
                         cudaFuncAttributeMaxDynamicSharedMemorySize, SMEM64);
    cudaFuncSetAttribute((const void*)tf32_mma_gemm<128, 2, 4, true>,
                         cudaFuncAttributeMaxDynamicSharedMemorySize, SMEM128);
    cudaFuncSetAttribute((const void*)tf32_mma_gemm<128, 2, 4, false>,
                         cudaFuncAttributeMaxDynamicSharedMemorySize, SMEM128);

    // Pre-round small B operands to tf32 (rna)
    round_tf32_kernel<<<(B_ * N_ * F_ / 4 + 255) / 256, 256>>>(X,  bX,  B_ * N_ * F_ / 4);
    round_tf32_kernel<<<(F_ * HD_ / 4 + 255) / 256, 256>>>(W1, bW1, F_ * HD_ / 4);
    round_tf32_kernel<<<(HD_ * HD_ / 4 + 255) / 256, 256>>>(W2, bW2, HD_ * HD_ / 4);

    // K1: T1 = A_hat @ X   (per batch 2048x2048 @ 2048x64) -> buf1 (rounded)
    tf32_mma_gemm<64, 4, 2, true><<<dim3(1, 16, 16), 256, SMEM64>>>(
        A_hat, bX, buf1, N_, F_,
        (long long)N_ * N_, (long long)N_ * F_, (long long)N_ * F_);
    // K2a: Z1 = T1 @ W1    (flat 32768x64 @ 64x256) -> buf2
    tf32_mma_gemm<128, 2, 4, false><<<dim3(2, 256, 1), 256, SMEM128>>>(
        buf1, bW1, buf2, F_, HD_, 0, 0, 0);
    // K2b: H1 = relu(LN(Z1 + b1)) -> buf1 (rounded: feeds K3 as B)
    bias_ln_relu_kernel<true><<<B_ * N_, 256>>>(buf2, b1, g1, be1, buf1);
    // K3: T2 = A_hat @ H1  (per batch 2048x2048 @ 2048x256) -> buf2 (rounded)
    tf32_mma_gemm<128, 2, 4, true><<<dim3(2, 16, 16), 256, SMEM128>>>(
        A_hat, buf1, buf2, N_, HD_,
        (long long)N_ * N_, (long long)N_ * HD_, (long long)N_ * HD_);
    // K4a: Z2 = T2 @ W2    (flat 32768x256 @ 256x256) -> buf1
    tf32_mma_gemm<128, 2, 4, false><<<dim3(2, 256, 1), 256, SMEM128>>>(
        buf2, bW2, buf1, HD_, HD_, 0, 0, 0);
    // K4b: H2 = relu(LN(Z2 + b2)) -> buf2
    bias_ln_relu_kernel<false><<<B_ * N_, 256>>>(buf1, b2, g2, be2, buf2);
    // K5: partial column sums -> part
    col_partial_kernel<<<dim3(B_, 16), 256>>>(buf2, part);
    // K6: mean + concat + heads -> out
    head_kernel<<<B_, 256>>>(part, gvec, Ws, bs, Wa, ba, out);
}

// round 5
// speedup vs baseline: 3.0877x; 1.0804x over previous
#include <cuda_runtime.h>
#include <cstdint>

// Problem constants
#define B_   16
#define N_   2048
#define F_   64
#define HD_  256
#define K_   128
#define G_   18
#define FUSE_ 274

// Scratch (allocation-free rule: __device__ globals)
__device__ float g_buf1[B_ * N_ * HD_];   // 32 MB
__device__ float g_buf2[B_ * N_ * HD_];   // 32 MB
__device__ float g_colsum[B_ * HD_];      // fused mean-readout accumulator
__device__ float g_bufX[B_ * N_ * F_];    // tf32-rounded X
__device__ float g_bufW1[F_ * HD_];
__device__ float g_bufW2[HD_ * HD_];

// Epilogue modes
#define EPI_STORE_RND 0   // store C, rna-rounded
#define EPI_LN_STORE  1   // bias+LN+ReLU, rna-rounded, store
#define EPI_LN_COLSUM 2   // bias+LN+ReLU, column-sum atomics only (no store)

// ---------------------------------------------------------------------------
// Helpers (baseline PTX only — harness compiles for compute_103 without 'a')
// ---------------------------------------------------------------------------
__device__ __forceinline__ uint32_t smem_u32(const void* p) {
    uint32_t a;
    asm("{ .reg .u64 t; cvta.to.shared.u64 t, %1; cvt.u32.u64 %0, t; }"
        : "=r"(a) : "l"(p));
    return a;
}

__device__ __forceinline__ void cp16(uint32_t dst, const float* src) {
    asm volatile("cp.async.cg.shared.global [%0], [%1], 16;"
                 :: "r"(dst), "l"(src) : "memory");
}
#define CP_COMMIT() asm volatile("cp.async.commit_group;" ::: "memory")
#define CP_WAIT(n)  asm volatile("cp.async.wait_group %0;" :: "n"(n) : "memory")

__device__ __forceinline__ float rna_tf32(float f) {
    uint32_t u;
    asm("cvt.rna.tf32.f32 %0, %1;" : "=r"(u) : "f"(f));
    return __uint_as_float(u);
}

__device__ __forceinline__ void mma8(float* c, const uint32_t* a, const uint32_t* b) {
    asm volatile(
        "mma.sync.aligned.m16n8k8.row.col.f32.tf32.tf32.f32 "
        "{%0,%1,%2,%3}, {%4,%5,%6,%7}, {%8,%9}, {%0,%1,%2,%3};"
        : "+f"(c[0]), "+f"(c[1]), "+f"(c[2]), "+f"(c[3])
        : "r"(a[0]), "r"(a[1]), "r"(a[2]), "r"(a[3]), "r"(b[0]), "r"(b[1]));
}

// ---------------------------------------------------------------------------
// Elementwise tf32 round (rna) into scratch, float4-vectorized
// ---------------------------------------------------------------------------
__global__ __launch_bounds__(256)
void round_tf32_kernel(const float* __restrict__ in, float* __restrict__ out, int n4) {
    int i = blockIdx.x * blockDim.x + threadIdx.x;
    if (i < n4) {
        float4 v = reinterpret_cast<const float4*>(in)[i];
        v.x = rna_tf32(v.x); v.y = rna_tf32(v.y);
        v.z = rna_tf32(v.z); v.w = rna_tf32(v.w);
        reinterpret_cast<float4*>(out)[i] = v;
    }
}

// ---------------------------------------------------------------------------
// TF32 mma.sync GEMM with fused epilogues: C[bz] = A[bz] @ Bm[bz]
// BM=128, BK=32, BN template (64 or 256). 256 threads = 8 warps.
// 3-stage cp.async pipe. No cvt in hot loop (A truncated, B pre-rounded).
// EPI_LN_*: BN must equal full row width (HD_=256); bias+LN+ReLU fused.
// ---------------------------------------------------------------------------
template <int BN, int WROWS, int WCOLS, int EPI>
__global__ __launch_bounds__(256)
void tf32_mma_gemm(const float* __restrict__ A, const float* __restrict__ Bm,
                   float* __restrict__ C, int Kd, int Ncols,
                   long long sA, long long sB, long long sC,
                   const float* __restrict__ bias,
                   const float* __restrict__ gamma,
                   const float* __restrict__ beta,
                   float* __restrict__ colsum) {
    constexpr int BM = 128, BK = 32, S = 3;
    constexpr int WM = BM / WROWS, WN = BN / WCOLS;
    constexpr int MF = WM / 16, NF = WN / 8;
    constexpr int AP = 36;          // A smem pitch: conflict-free frag reads
    constexpr int BP = BN + 8;      // B smem pitch
    constexpr int AS_F = BM * AP;
    constexpr int BS_F = BK * BP;
    constexpr int ST_F = AS_F + BS_F;
    constexpr int EP = 260;         // epilogue tile pitch (BN=256 only)

    extern __shared__ float smem[];
    const uint32_t sbase = smem_u32(smem);
    __shared__ float sBias[HD_], sGamma[HD_], sBeta[HD_];

    const int tid  = threadIdx.x;
    const int lane = tid & 31, wid = tid >> 5;
    const int wm = (wid / WCOLS) * WM;
    const int wn = (wid % WCOLS) * WN;

    if (EPI != EPI_STORE_RND) {
        sBias[tid]  = bias[tid & (HD_ - 1)];
        sGamma[tid] = gamma[tid & (HD_ - 1)];
        sBeta[tid]  = beta[tid & (HD_ - 1)];
    }

    const long long bz = blockIdx.z;
    const float* Ab = A + bz * sA + (long long)blockIdx.y * BM * Kd;
    const float* Bb = Bm + bz * sB + blockIdx.x * BN;
    float*       Cb = C + bz * sC + (long long)blockIdx.y * BM * Ncols
                        + blockIdx.x * BN;

    float acc[MF][NF][4];
#pragma unroll
    for (int i = 0; i < MF; i++)
#pragma unroll
        for (int j = 0; j < NF; j++)
#pragma unroll
            for (int r = 0; r < 4; r++) acc[i][j][r] = 0.f;

    const int nch = Kd >> 5;

    auto load_stage = [&](int s, int kc) {
        const float* Ak = Ab + kc * BK;
#pragma unroll
        for (int i = 0; i < 4; i++) {
            int idx = tid + i * 256;
            int r = idx >> 3, c4 = idx & 7;
            uint32_t dst = sbase + (uint32_t)(s * ST_F + r * AP + c4 * 4) * 4u;
            cp16(dst, Ak + (long long)r * Kd + c4 * 4);
        }
        const float* Bk = Bb + (long long)(kc * BK) * Ncols;
        constexpr int BI = (BN * BK) / (4 * 256);
        constexpr int C4 = BN / 4;
#pragma unroll
        for (int i = 0; i < BI; i++) {
            int idx = tid + i * 256;
            int r = idx / C4, c4 = idx % C4;
            uint32_t dst = sbase +
                (uint32_t)(s * ST_F + AS_F + r * BP + c4 * 4) * 4u;
            cp16(dst, Bk + (long long)r * Ncols + c4 * 4);
        }
    };

    auto compute_stage = [&](int s) {
        const uint32_t* As = reinterpret_cast<const uint32_t*>(smem + s * ST_F);
        const uint32_t* Bs = reinterpret_cast<const uint32_t*>(smem + s * ST_F + AS_F);
#pragma unroll
        for (int kk = 0; kk < 4; kk++) {
            const int k0 = kk * 8;
            uint32_t af[MF][4], bf[NF][2];
#pragma unroll
            for (int mf = 0; mf < MF; mf++) {
                int m = wm + mf * 16 + (lane >> 2);
                int k = k0 + (lane & 3);
                af[mf][0] = As[m * AP + k];
                af[mf][1] = As[(m + 8) * AP + k];
                af[mf][2] = As[m * AP + k + 4];
                af[mf][3] = As[(m + 8) * AP + k + 4];
            }
#pragma unroll
            for (int nf = 0; nf < NF; nf++) {
                int n = wn + nf * 8 + (lane >> 2);
                int k = k0 + (lane & 3);
                bf[nf][0] = Bs[k * BP + n];
                bf[nf][1] = Bs[(k + 4) * BP + n];
            }
#pragma unroll
            for (int mf = 0; mf < MF; mf++)
#pragma unroll
                for (int nf = 0; nf < NF; nf++)
                    mma8(acc[mf][nf], af[mf], bf[nf]);
        }
    };

#pragma unroll
    for (int s = 0; s < S - 1; s++) {
        if (s < nch) load_stage(s, s);
        CP_COMMIT();
    }
    for (int kc = 0; kc < nch; kc++) {
        CP_WAIT(S - 2);
        __syncthreads();
        if (kc + S - 1 < nch) load_stage((kc + S - 1) % S, kc + S - 1);
        CP_COMMIT();
        compute_stage(kc % S);
        __syncthreads();
    }

    if (EPI == EPI_STORE_RND) {
#pragma unroll
        for (int mf = 0; mf < MF; mf++) {
#pragma unroll
            for (int nf = 0; nf < NF; nf++) {
                int row = wm + mf * 16 + (lane >> 2);
                int col = wn + nf * 8 + (lane & 3) * 2;
                float2 v0 = make_float2(rna_tf32(acc[mf][nf][0]),
                                        rna_tf32(acc[mf][nf][1]));
                float2 v1 = make_float2(rna_tf32(acc[mf][nf][2]),
                                        rna_tf32(acc[mf][nf][3]));
                *reinterpret_cast<float2*>(Cb + (long long)row * Ncols + col) = v0;
                *reinterpret_cast<float2*>(Cb + (long long)(row + 8) * Ncols + col) = v1;
            }
        }
        return;
    }

    // ---- Fused bias + LayerNorm + ReLU epilogue (BN == HD_ == 256) ----
    // Stash accumulators into smem tile [128][EP]
#pragma unroll
    for (int mf = 0; mf < MF; mf++) {
#pragma unroll
        for (int nf = 0; nf < NF; nf++) {
            int row = wm + mf * 16 + (lane >> 2);
            int col = wn + nf * 8 + (lane & 3) * 2;
            smem[row * EP + col]     = acc[mf][nf][0];
            smem[row * EP + col + 1] = acc[mf][nf][1];
            smem[(row + 8) * EP + col]     = acc[mf][nf][2];
            smem[(row + 8) * EP + col + 1] = acc[mf][nf][3];
        }
    }
    __syncthreads();

    // Each warp handles 16 rows; lane owns 8 columns (lane*8 .. lane*8+7)
    const float inv = 1.f / (float)HD_;
#pragma unroll 1
    for (int rr = 0; rr < 16; rr++) {
        const int r = wid * 16 + rr;
        float x[8];
        float4 v0 = *reinterpret_cast<float4*>(&smem[r * EP + lane * 8]);
        float4 v1 = *reinterpret_cast<float4*>(&smem[r * EP + lane * 8 + 4]);
        x[0] = v0.x; x[1] = v0.y; x[2] = v0.z; x[3] = v0.w;
        x[4] = v1.x; x[5] = v1.y; x[6] = v1.z; x[7] = v1.w;
        float s = 0.f, s2 = 0.f;
#pragma unroll
        for (int j = 0; j < 8; j++) {
            x[j] += sBias[lane * 8 + j];
            s += x[j]; s2 += x[j] * x[j];
        }
#pragma unroll
        for (int o = 16; o; o >>= 1) {
            s  += __shfl_xor_sync(0xFFFFFFFFu, s, o);
            s2 += __shfl_xor_sync(0xFFFFFFFFu, s2, o);
        }
        float mu = s * inv;
        float rstd = rsqrtf(s2 * inv - mu * mu + 1e-5f);
        float y[8];
#pragma unroll
        for (int j = 0; j < 8; j++) {
            float v = (x[j] - mu) * rstd * sGamma[lane * 8 + j] + sBeta[lane * 8 + j];
            y[j] = fmaxf(v, 0.f);
        }
        if (EPI == EPI_LN_STORE) {
#pragma unroll
            for (int j = 0; j < 8; j++) y[j] = rna_tf32(y[j]);
            float* crow = Cb + (long long)r * Ncols + lane * 8;
            *reinterpret_cast<float4*>(crow)     = make_float4(y[0], y[1], y[2], y[3]);
            *reinterpret_cast<float4*>(crow + 4) = make_float4(y[4], y[5], y[6], y[7]);
        } else {  // EPI_LN_COLSUM: write back for column reduction
            *reinterpret_cast<float4*>(&smem[r * EP + lane * 8]) =
                make_float4(y[0], y[1], y[2], y[3]);
            *reinterpret_cast<float4*>(&smem[r * EP + lane * 8 + 4]) =
                make_float4(y[4], y[5], y[6], y[7]);
        }
    }

    if (EPI == EPI_LN_COLSUM) {
        __syncthreads();
        float s = 0.f;
#pragma unroll 8
        for (int r = 0; r < BM; r++) s += smem[r * EP + tid];
        const int b = (int)(blockIdx.y >> 4);   // 128-row tiles, 16 per batch
        atomicAdd(&colsum[b * HD_ + tid], s);
    }
}

// ---------------------------------------------------------------------------
// Head: colsum -> mean, concat global_vec, two small linear heads.
// ---------------------------------------------------------------------------
__global__ __launch_bounds__(256)
void head_kernel(const float* __restrict__ colsum, const float* __restrict__ gvec,
                 const float* __restrict__ Ws, const float* __restrict__ bs,
                 const float* __restrict__ Wa, const float* __restrict__ ba,
                 float* __restrict__ out) {
    int b = blockIdx.x, t = threadIdx.x;
    __shared__ float fused[FUSE_];
    fused[t] = colsum[b * HD_ + t] * (1.f / (float)N_);
    if (t < G_) fused[HD_ + t] = gvec[b * G_ + t];
    __syncthreads();

    if (t < K_) {
        float acc = ba[t];
#pragma unroll 4
        for (int i = 0; i < FUSE_; i++) acc += fused[i] * Wa[i * K_ + t];
        out[B_ + b * K_ + t] = acc;
    } else if (t == K_) {
        float acc = bs[0];
        for (int i = 0; i < FUSE_; i++) acc += fused[i] * Ws[i];
        out[b] = acc;
    }
}

// ---------------------------------------------------------------------------
extern "C" void kernel_launch(void* const* d_in, const int* in_sizes, int n_in,
                              void* d_out, int out_size) {
    const float* A_hat = (const float*)d_in[0];
    const float* X     = (const float*)d_in[1];
    const float* gvec  = (const float*)d_in[2];
    const float* W1    = (const float*)d_in[3];
    const float* b1    = (const float*)d_in[4];
    const float* g1    = (const float*)d_in[5];
    const float* be1   = (const float*)d_in[6];
    const float* W2    = (const float*)d_in[7];
    const float* b2    = (const float*)d_in[8];
    const float* g2    = (const float*)d_in[9];
    const float* be2   = (const float*)d_in[10];
    const float* Ws    = (const float*)d_in[11];
    const float* bs    = (const float*)d_in[12];
    const float* Wa    = (const float*)d_in[13];
    const float* ba    = (const float*)d_in[14];
    float* out = (float*)d_out;

    float *buf1, *buf2, *csum, *bX, *bW1, *bW2;
    cudaGetSymbolAddress((void**)&buf1, g_buf1);
    cudaGetSymbolAddress((void**)&buf2, g_buf2);
    cudaGetSymbolAddress((void**)&csum, g_colsum);
    cudaGetSymbolAddress((void**)&bX,  g_bufX);
    cudaGetSymbolAddress((void**)&bW1, g_bufW1);
    cudaGetSymbolAddress((void**)&bW2, g_bufW2);

    constexpr int SMEM64  = 3 * (128 * 36 + 32 * 72)  * 4;  //  82944
    constexpr int SMEM256 = 3 * (128 * 36 + 32 * 264) * 4;  // 156672
    cudaFuncSetAttribute((const void*)tf32_mma_gemm<64, 4, 2, EPI_STORE_RND>,
                         cudaFuncAttributeMaxDynamicSharedMemorySize, SMEM64);
    cudaFuncSetAttribute((const void*)tf32_mma_gemm<256, 2, 4, EPI_STORE_RND>,
                         cudaFuncAttributeMaxDynamicSharedMemorySize, SMEM256);
    cudaFuncSetAttribute((const void*)tf32_mma_gemm<256, 2, 4, EPI_LN_STORE>,
                         cudaFuncAttributeMaxDynamicSharedMemorySize, SMEM256);
    cudaFuncSetAttribute((const void*)tf32_mma_gemm<256, 2, 4, EPI_LN_COLSUM>,
                         cudaFuncAttributeMaxDynamicSharedMemorySize, SMEM256);

    // Pre-round small B operands; zero the colsum accumulator
    round_tf32_kernel<<<(B_ * N_ * F_ / 4 + 255) / 256, 256>>>(X,  bX,  B_ * N_ * F_ / 4);
    round_tf32_kernel<<<(F_ * HD_ / 4 + 255) / 256, 256>>>(W1, bW1, F_ * HD_ / 4);
    round_tf32_kernel<<<(HD_ * HD_ / 4 + 255) / 256, 256>>>(W2, bW2, HD_ * HD_ / 4);
    cudaMemsetAsync(csum, 0, B_ * HD_ * sizeof(float));

    // K1: T1 = A_hat @ X  (per batch 2048x2048 @ 2048x64) -> buf1 (rounded)
    tf32_mma_gemm<64, 4, 2, EPI_STORE_RND><<<dim3(1, 16, 16), 256, SMEM64>>>(
        A_hat, bX, buf1, N_, F_,
        (long long)N_ * N_, (long long)N_ * F_, (long long)N_ * F_,
        nullptr, nullptr, nullptr, nullptr);
    // K2: H1 = relu(LN(T1@W1 + b1)) (flat 32768x64 @ 64x256) -> buf2 (rounded)
    tf32_mma_gemm<256, 2, 4, EPI_LN_STORE><<<dim3(1, 256, 1), 256, SMEM256>>>(
        buf1, bW1, buf2, F_, HD_, 0, 0, 0, b1, g1, be1, nullptr);
    // K3: T2 = A_hat @ H1 (per batch 2048x2048 @ 2048x256) -> buf1 (rounded)
    tf32_mma_gemm<256, 2, 4, EPI_STORE_RND><<<dim3(1, 16, 16), 256, SMEM256>>>(
        A_hat, buf2, buf1, N_, HD_,
        (long long)N_ * N_, (long long)N_ * HD_, (long long)N_ * HD_,
        nullptr, nullptr, nullptr, nullptr);
    // K4: colsum += colsums(relu(LN(T2@W2 + b2))) — no tensor store
    tf32_mma_gemm<256, 2, 4, EPI_LN_COLSUM><<<dim3(1, 256, 1), 256, SMEM256>>>(
        buf1, bW2, nullptr, HD_, HD_, 0, 0, 0, b2, g2, be2, csum);
    // K5: mean + concat + heads -> out
    head_kernel<<<B_, 256>>>(csum, gvec, Ws, bs, Wa, ba, out);
}